// round 7
// baseline (speedup 1.0000x reference)
#include <cuda_runtime.h>

// SigmoidFlow: B=2048, D=512, NDIM=16
// out[0..B*D) = xnew ; out[B*D..B*B*D? no: B*D..B*D+B) = logdet
//
// R7: fully-coalesced loads via per-warp smem staging.
// Warp-iteration tile = 8 elements = 384 floats = 96 float4 = 1536 B
// contiguous. Lane L loads float4 {L, 32+L, 64+L} (3 dense LDG.128, 100%
// sectors), STS to per-warp buffer, LDS in element layout (conflict-free),
// then R2 math (single-rcp cofactor sigmoids, 3 logs/element).

#define TPB 128

__device__ __forceinline__ float fast_rcp(float v) {
    float r; asm("rcp.approx.f32 %0, %1;" : "=f"(r) : "f"(v)); return r;
}

__device__ __forceinline__ void sf_compute(float4 av, float4 bv, float4 wv, float xv,
                                           float& Wl, float& Sl, float& Dl)
{
    float a_[4] = {av.x, av.y, av.z, av.w};
    float b_[4] = {bv.x, bv.y, bv.z, bv.w};
    float wl[4] = {wv.x, wv.y, wv.z, wv.w};

    float asp[4], t[4], onet[4], ew[4];
    #pragma unroll
    for (int j = 0; j < 4; ++j) {
        float ea  = __expf(a_[j]);
        asp[j]    = __logf(1.0f + ea);            // softplus
        float pre = fmaf(asp[j], xv, b_[j]);
        t[j]      = __expf(-pre);
        onet[j]   = 1.0f + t[j];
        ew[j]     = __expf(wl[j]);
    }
    float p01 = onet[0] * onet[1];
    float p23 = onet[2] * onet[3];
    float iP  = fast_rcp(p01 * p23);
    float h0  = (onet[1] * p23) * iP;             // sigm_0
    float h1  = (onet[0] * p23) * iP;
    float h2  = (p01 * onet[3]) * iP;
    float h3  = (p01 * onet[2]) * iP;

    Wl = (ew[0] + ew[1]) + (ew[2] + ew[3]);
    Sl = fmaf(ew[3], h3, fmaf(ew[2], h2, fmaf(ew[1], h1, ew[0] * h0)));
    float d0 = (ew[0] * asp[0]) * (t[0] * h0 * h0);
    float d1 = (ew[1] * asp[1]) * (t[1] * h1 * h1);
    float d2 = (ew[2] * asp[2]) * (t[2] * h2 * h2);
    float d3 = (ew[3] * asp[3]) * (t[3] * h3 * h3);
    Dl = (d0 + d1) + (d2 + d3);
}

// Requires D % 32 == 0.
__global__ __launch_bounds__(TPB, 10)
void sf_kernel(const float* __restrict__ x,
               const float* __restrict__ logdet_in,
               const float* __restrict__ dsp,
               float* __restrict__ out,
               int B, int D)
{
    __shared__ float4 buf[4][96];        // 1536 B per warp
    __shared__ float  s_part[4];

    const int b    = blockIdx.x;
    const int tid  = threadIdx.x;
    const int lane = tid & 31;
    const int w    = tid >> 5;           // 0..3
    const int q    = lane & 3;
    const int esub = lane >> 2;          // 0..7

    const float ONE_MD = 1.0f - 1e-6f;
    const float HALF_D = 0.5e-6f;
    const float LOG1MD = -1.0000005e-6f;

    const float*  xrow = x + (long long)b * D;
    const float4* prow = (const float4*)(dsp + (long long)b * D * 48);
    float*        orow = out + (long long)b * D;

    const int niter = D >> 5;            // elements per iter: 32 (8 per warp)

    // prefetch iter 0 tile (contiguous 1536 B per warp)
    const float4* p0 = prow + w * 96 + lane;
    float4 r0 = __ldg(p0);
    float4 r1 = __ldg(p0 + 32);
    float4 r2 = __ldg(p0 + 64);

    float acc = 0.0f;

    for (int it = 0; it < niter; ++it) {
        // stage current tile
        buf[w][lane]      = r0;
        buf[w][32 + lane] = r1;
        buf[w][64 + lane] = r2;

        // prefetch next tile while this one is consumed
        if (it + 1 < niter) {
            const float4* pn = prow + (it + 1) * 384 + w * 96 + lane;
            r0 = __ldg(pn);
            r1 = __ldg(pn + 32);
            r2 = __ldg(pn + 64);
        }
        __syncwarp();

        const float4 av = buf[w][esub * 12 + q];
        const float4 bv = buf[w][esub * 12 + 4 + q];
        const float4 wv = buf[w][esub * 12 + 8 + q];

        const int d = it * 32 + w * 8 + esub;
        const float xv = __ldg(xrow + d);

        float Wl, Sl, Dl;
        sf_compute(av, bv, wv, xv, Wl, Sl, Dl);

        // reduce (W,S,D) across the 4-lane group
        Wl += __shfl_xor_sync(0xffffffffu, Wl, 1);
        Sl += __shfl_xor_sync(0xffffffffu, Sl, 1);
        Dl += __shfl_xor_sync(0xffffffffu, Dl, 1);
        Wl += __shfl_xor_sync(0xffffffffu, Wl, 2);
        Sl += __shfl_xor_sync(0xffffffffu, Sl, 2);
        Dl += __shfl_xor_sync(0xffffffffu, Dl, 2);

        const float hw = HALF_D * Wl;
        const float N1 = fmaf(ONE_MD, Sl, hw);
        const float N2 = fmaf(ONE_MD, Wl - Sl, hw);
        const float l1 = __logf(N1);
        const float l2 = __logf(N2);
        const float l3 = __logf(Dl * Wl);

        if (q == 0) orow[d] = l1 - l2;             // xnew
        acc += l3 - l1 - l2 + LOG1MD;              // replicated x4

        __syncwarp();   // all lanes done reading buf before next STS
    }

    // warp + block reduction (each element counted 4x -> scale 0.25)
    #pragma unroll
    for (int m = 16; m >= 1; m >>= 1)
        acc += __shfl_xor_sync(0xffffffffu, acc, m);
    if (lane == 0) s_part[w] = acc;
    __syncthreads();

    if (tid == 0) {
        float v = (s_part[0] + s_part[1]) + (s_part[2] + s_part[3]);
        out[(long long)B * D + b] = 0.25f * v + __ldg(logdet_in + b);
    }
}

// Generic fallback for D not a multiple of 32 (strided loads, same math).
__global__ __launch_bounds__(TPB)
void sf_kernel_gen(const float* __restrict__ x,
                   const float* __restrict__ logdet_in,
                   const float* __restrict__ dsp,
                   float* __restrict__ out,
                   int B, int D)
{
    const int b    = blockIdx.x;
    const int tid  = threadIdx.x;
    const int lane = tid & 31;
    const int wid  = tid >> 5;
    const int q    = lane & 3;
    const int e0   = wid * 8 + (lane >> 2);

    const float ONE_MD = 1.0f - 1e-6f;
    const float HALF_D = 0.5e-6f;
    const float LOG1MD = -1.0000005e-6f;

    __shared__ float s_part[4];
    float acc = 0.0f;

    const int niter = (D + 31) / 32;
    for (int it = 0; it < niter; ++it) {
        const int d = it * 32 + e0;
        if (d < D) {
            const long long idx = (long long)b * D + d;
            const float4* p = (const float4*)(dsp + idx * 48);
            const float4 av = __ldg(p + q);
            const float4 bv = __ldg(p + 4 + q);
            const float4 wv = __ldg(p + 8 + q);
            const float  xv = __ldg(x + idx);

            float Wl, Sl, Dl;
            sf_compute(av, bv, wv, xv, Wl, Sl, Dl);

            Wl += __shfl_xor_sync(0xffffffffu, Wl, 1);
            Sl += __shfl_xor_sync(0xffffffffu, Sl, 1);
            Dl += __shfl_xor_sync(0xffffffffu, Dl, 1);
            Wl += __shfl_xor_sync(0xffffffffu, Wl, 2);
            Sl += __shfl_xor_sync(0xffffffffu, Sl, 2);
            Dl += __shfl_xor_sync(0xffffffffu, Dl, 2);

            const float hw = HALF_D * Wl;
            const float N1 = fmaf(ONE_MD, Sl, hw);
            const float N2 = fmaf(ONE_MD, Wl - Sl, hw);
            const float l1 = __logf(N1);
            const float l2 = __logf(N2);
            const float l3 = __logf(Dl * Wl);

            if (q == 0) out[idx] = l1 - l2;
            acc += l3 - l1 - l2 + LOG1MD;
        }
    }

    #pragma unroll
    for (int m = 16; m >= 1; m >>= 1)
        acc += __shfl_xor_sync(0xffffffffu, acc, m);
    if (lane == 0) s_part[wid] = acc;
    __syncthreads();

    if (tid == 0) {
        float v = (s_part[0] + s_part[1]) + (s_part[2] + s_part[3]);
        out[(long long)B * D + b] = 0.25f * v + __ldg(logdet_in + b);
    }
}

extern "C" void kernel_launch(void* const* d_in, const int* in_sizes, int n_in,
                              void* d_out, int out_size)
{
    const float* x   = (const float*)d_in[0];   // (B, D)
    const float* ld  = (const float*)d_in[1];   // (B,)
    const float* dsp = (const float*)d_in[2];   // (B, D, 48)
    float* out = (float*)d_out;

    const int B = in_sizes[1];
    const int D = in_sizes[0] / B;

    if ((D & 31) == 0)
        sf_kernel<<<B, TPB>>>(x, ld, dsp, out, B, D);
    else
        sf_kernel_gen<<<B, TPB>>>(x, ld, dsp, out, B, D);
}

// round 8
// speedup vs baseline: 1.1032x; 1.1032x over previous
#include <cuda_runtime.h>

// SigmoidFlow: B=2048, D=512, NDIM=16
// out[0..B*D) = xnew ; out[B*D..B*D+B) = logdet
//
// R8: lock in R4 (best wall 37.3us): TPB=128, one row/CTA, single wave,
// .cs streaming loads, q-split (4 lanes/element keeps L1 wavefronts at
// 3/elem). Micro-opts: guard-free loop, pointer strength reduction (no
// per-iter 64-bit index math), flat final reduction.
// Math = R2: single-rcp cofactor sigmoids, 3 logs/element.

#define TPB 128

__device__ __forceinline__ float fast_rcp(float v) {
    float r; asm("rcp.approx.f32 %0, %1;" : "=f"(r) : "f"(v)); return r;
}

__device__ __forceinline__ void sf_compute(float4 av, float4 bv, float4 wv, float xv,
                                           float& Wl, float& Sl, float& Dl)
{
    float a_[4] = {av.x, av.y, av.z, av.w};
    float b_[4] = {bv.x, bv.y, bv.z, bv.w};
    float wl[4] = {wv.x, wv.y, wv.z, wv.w};

    float asp[4], t[4], onet[4], ew[4];
    #pragma unroll
    for (int j = 0; j < 4; ++j) {
        float ea  = __expf(a_[j]);
        asp[j]    = __logf(1.0f + ea);            // softplus
        float pre = fmaf(asp[j], xv, b_[j]);
        t[j]      = __expf(-pre);
        onet[j]   = 1.0f + t[j];
        ew[j]     = __expf(wl[j]);
    }
    float p01 = onet[0] * onet[1];
    float p23 = onet[2] * onet[3];
    float iP  = fast_rcp(p01 * p23);
    float h0  = (onet[1] * p23) * iP;             // sigm_0
    float h1  = (onet[0] * p23) * iP;
    float h2  = (p01 * onet[3]) * iP;
    float h3  = (p01 * onet[2]) * iP;

    Wl = (ew[0] + ew[1]) + (ew[2] + ew[3]);
    Sl = fmaf(ew[3], h3, fmaf(ew[2], h2, fmaf(ew[1], h1, ew[0] * h0)));
    float d0 = (ew[0] * asp[0]) * (t[0] * h0 * h0);
    float d1 = (ew[1] * asp[1]) * (t[1] * h1 * h1);
    float d2 = (ew[2] * asp[2]) * (t[2] * h2 * h2);
    float d3 = (ew[3] * asp[3]) * (t[3] * h3 * h3);
    Dl = (d0 + d1) + (d2 + d3);
}

// Requires D % 32 == 0.
__global__ __launch_bounds__(TPB, 16)
void sf_kernel(const float* __restrict__ x,
               const float* __restrict__ logdet_in,
               const float* __restrict__ dsp,
               float* __restrict__ out,
               int B, int D)
{
    const int b    = blockIdx.x;
    const int tid  = threadIdx.x;
    const int lane = tid & 31;
    const int wid  = tid >> 5;                 // 0..3
    const int q    = lane & 3;                 // component group
    const int e0   = wid * 8 + (lane >> 2);    // 0..31

    const float ONE_MD = 1.0f - 1e-6f;
    const float HALF_D = 0.5e-6f;
    const float LOG1MD = -1.0000005e-6f;

    __shared__ float s_part[4];

    // strength-reduced pointers: advance by fixed stride each iteration
    const float*  xp = x   + (long long)b * D + e0;
    const float4* pp = (const float4*)(dsp + ((long long)b * D + e0) * 48) + q;
    float*        op = out + (long long)b * D + e0;

    float acc = 0.0f;

    const int niter = D >> 5;
    for (int it = 0; it < niter; ++it) {
        const float4 av = __ldcs(pp);
        const float4 bv = __ldcs(pp + 4);
        const float4 wv = __ldcs(pp + 8);
        const float  xv = __ldcs(xp);

        float Wl, Sl, Dl;
        sf_compute(av, bv, wv, xv, Wl, Sl, Dl);

        // reduce (W,S,D) across the 4-lane group
        Wl += __shfl_xor_sync(0xffffffffu, Wl, 1);
        Sl += __shfl_xor_sync(0xffffffffu, Sl, 1);
        Dl += __shfl_xor_sync(0xffffffffu, Dl, 1);
        Wl += __shfl_xor_sync(0xffffffffu, Wl, 2);
        Sl += __shfl_xor_sync(0xffffffffu, Sl, 2);
        Dl += __shfl_xor_sync(0xffffffffu, Dl, 2);

        const float hw = HALF_D * Wl;
        const float N1 = fmaf(ONE_MD, Sl, hw);
        const float N2 = fmaf(ONE_MD, Wl - Sl, hw);
        const float l1 = __logf(N1);
        const float l2 = __logf(N2);
        const float l3 = __logf(Dl * Wl);

        if (q == 0) __stcs(op, l1 - l2);           // xnew
        acc += l3 - l1 - l2 + LOG1MD;              // replicated x4

        pp += 32 * 12;
        xp += 32;
        op += 32;
    }

    // warp + block reduction (each element counted 4x -> scale 0.25)
    #pragma unroll
    for (int m = 16; m >= 1; m >>= 1)
        acc += __shfl_xor_sync(0xffffffffu, acc, m);
    if (lane == 0) s_part[wid] = acc;
    __syncthreads();

    if (tid == 0) {
        float v = (s_part[0] + s_part[1]) + (s_part[2] + s_part[3]);
        out[(long long)B * D + b] = 0.25f * v + __ldg(logdet_in + b);
    }
}

// Generic fallback for D not a multiple of 32.
__global__ __launch_bounds__(TPB)
void sf_kernel_gen(const float* __restrict__ x,
                   const float* __restrict__ logdet_in,
                   const float* __restrict__ dsp,
                   float* __restrict__ out,
                   int B, int D)
{
    const int b    = blockIdx.x;
    const int tid  = threadIdx.x;
    const int lane = tid & 31;
    const int wid  = tid >> 5;
    const int q    = lane & 3;
    const int e0   = wid * 8 + (lane >> 2);

    const float ONE_MD = 1.0f - 1e-6f;
    const float HALF_D = 0.5e-6f;
    const float LOG1MD = -1.0000005e-6f;

    __shared__ float s_part[4];
    float acc = 0.0f;

    const int niter = (D + 31) / 32;
    for (int it = 0; it < niter; ++it) {
        const int d = it * 32 + e0;
        if (d < D) {
            const long long idx = (long long)b * D + d;
            const float4* p = (const float4*)(dsp + idx * 48);
            const float4 av = __ldg(p + q);
            const float4 bv = __ldg(p + 4 + q);
            const float4 wv = __ldg(p + 8 + q);
            const float  xv = __ldg(x + idx);

            float Wl, Sl, Dl;
            sf_compute(av, bv, wv, xv, Wl, Sl, Dl);

            Wl += __shfl_xor_sync(0xffffffffu, Wl, 1);
            Sl += __shfl_xor_sync(0xffffffffu, Sl, 1);
            Dl += __shfl_xor_sync(0xffffffffu, Dl, 1);
            Wl += __shfl_xor_sync(0xffffffffu, Wl, 2);
            Sl += __shfl_xor_sync(0xffffffffu, Sl, 2);
            Dl += __shfl_xor_sync(0xffffffffu, Dl, 2);

            const float hw = HALF_D * Wl;
            const float N1 = fmaf(ONE_MD, Sl, hw);
            const float N2 = fmaf(ONE_MD, Wl - Sl, hw);
            const float l1 = __logf(N1);
            const float l2 = __logf(N2);
            const float l3 = __logf(Dl * Wl);

            if (q == 0) out[idx] = l1 - l2;
            acc += l3 - l1 - l2 + LOG1MD;
        }
    }

    #pragma unroll
    for (int m = 16; m >= 1; m >>= 1)
        acc += __shfl_xor_sync(0xffffffffu, acc, m);
    if (lane == 0) s_part[wid] = acc;
    __syncthreads();

    if (tid == 0) {
        float v = (s_part[0] + s_part[1]) + (s_part[2] + s_part[3]);
        out[(long long)B * D + b] = 0.25f * v + __ldg(logdet_in + b);
    }
}

extern "C" void kernel_launch(void* const* d_in, const int* in_sizes, int n_in,
                              void* d_out, int out_size)
{
    const float* x   = (const float*)d_in[0];   // (B, D)
    const float* ld  = (const float*)d_in[1];   // (B,)
    const float* dsp = (const float*)d_in[2];   // (B, D, 48)
    float* out = (float*)d_out;

    const int B = in_sizes[1];
    const int D = in_sizes[0] / B;

    if ((D & 31) == 0)
        sf_kernel<<<B, TPB>>>(x, ld, dsp, out, B, D);
    else
        sf_kernel_gen<<<B, TPB>>>(x, ld, dsp, out, B, D);
}

// round 9
// speedup vs baseline: 1.1113x; 1.0073x over previous
#include <cuda_runtime.h>

// SigmoidFlow: B=2048, D=512, NDIM=16
// out[0..B*D) = xnew ; out[B*D..B*D+B) = logdet
//
// R9 = R1 launch/memory shape (TPB=512, best profiled: ncu 37.5us, HBM
// 5654 GB/s) + R2 math (single-rcp cofactor sigmoids, 3 logs/element;
// ~17% fewer MUFU ops than R1's math). Everything else identical to R1.

#define TPB 512

__device__ __forceinline__ float fast_rcp(float v) {
    float r; asm("rcp.approx.f32 %0, %1;" : "=f"(r) : "f"(v)); return r;
}

__global__ __launch_bounds__(TPB)
void sigmoid_flow_kernel(const float* __restrict__ x,
                         const float* __restrict__ logdet_in,
                         const float* __restrict__ dsp,
                         float* __restrict__ out,
                         int B, int D)
{
    const int b    = blockIdx.x;
    const int tid  = threadIdx.x;
    const int lane = tid & 31;
    const int wid  = tid >> 5;          // 0..15
    const int q    = lane & 3;          // component-group within element
    const int esub = lane >> 2;         // 0..7 element within warp
    const int e_in_block = wid * 8 + esub;   // 0..127

    const float ONE_MD = 1.0f - 1e-6f;
    const float HALF_D = 0.5e-6f;
    const float LOG1MD = -1.0000005e-6f;    // log(1-1e-6)

    __shared__ float s_part[TPB / 32];

    float acc = 0.0f;   // per-thread logdet partial (each element counted 4x)

    const int niter = (D + 127) / 128;
    for (int it = 0; it < niter; ++it) {
        const int d = it * 128 + e_in_block;
        if (d < D) {
            const long long idx = (long long)b * D + d;
            // dsparams row: 48 floats = 12 float4, 16B-aligned
            const float4* p = (const float4*)(dsp + idx * 48);
            const float4 av = p[q];        // a_  components 4q..4q+3
            const float4 bv = p[4 + q];    // b_
            const float4 wv = p[8 + q];    // w_logits
            const float xv = __ldg(x + idx);

            float a_[4] = {av.x, av.y, av.z, av.w};
            float bb[4] = {bv.x, bv.y, bv.z, bv.w};
            float wl[4] = {wv.x, wv.y, wv.z, wv.w};

            float asp[4], t[4], onet[4], ew[4];
            #pragma unroll
            for (int j = 0; j < 4; ++j) {
                float ea  = __expf(a_[j]);
                asp[j]    = __logf(1.0f + ea);            // softplus
                float pre = fmaf(asp[j], xv, bb[j]);
                t[j]      = __expf(-pre);
                onet[j]   = 1.0f + t[j];
                ew[j]     = __expf(wl[j]);
            }
            // single-rcp cofactor sigmoids: h_j = 1/(1+t_j)
            float p01 = onet[0] * onet[1];
            float p23 = onet[2] * onet[3];
            float iP  = fast_rcp(p01 * p23);
            float h0  = (onet[1] * p23) * iP;
            float h1  = (onet[0] * p23) * iP;
            float h2  = (p01 * onet[3]) * iP;
            float h3  = (p01 * onet[2]) * iP;

            float Wl = (ew[0] + ew[1]) + (ew[2] + ew[3]);
            float Sl = fmaf(ew[3], h3, fmaf(ew[2], h2, fmaf(ew[1], h1, ew[0] * h0)));
            float d0 = (ew[0] * asp[0]) * (t[0] * h0 * h0);
            float d1 = (ew[1] * asp[1]) * (t[1] * h1 * h1);
            float d2 = (ew[2] * asp[2]) * (t[2] * h2 * h2);
            float d3 = (ew[3] * asp[3]) * (t[3] * h3 * h3);
            float Dl = (d0 + d1) + (d2 + d3);

            // reduce the 3 sums across the 4-lane group (xor 1, xor 2)
            Wl += __shfl_xor_sync(0xffffffffu, Wl, 1);
            Sl += __shfl_xor_sync(0xffffffffu, Sl, 1);
            Dl += __shfl_xor_sync(0xffffffffu, Dl, 1);
            Wl += __shfl_xor_sync(0xffffffffu, Wl, 2);
            Sl += __shfl_xor_sync(0xffffffffu, Sl, 2);
            Dl += __shfl_xor_sync(0xffffffffu, Dl, 2);

            // xnew = log(N1) - log(N2); logdet term = log(Dl*Wl) - log N1 - log N2 + log(1-d)
            const float hw = HALF_D * Wl;
            const float N1 = fmaf(ONE_MD, Sl, hw);
            const float N2 = fmaf(ONE_MD, Wl - Sl, hw);
            const float l1 = __logf(N1);
            const float l2 = __logf(N2);
            const float l3 = __logf(Dl * Wl);

            if (q == 0) out[idx] = l1 - l2;              // xnew
            acc += l3 - l1 - l2 + LOG1MD;                // replicated on 4 lanes
        }
    }

    // warp reduction (each element counted 4x -> scale by 0.25 at the end)
    #pragma unroll
    for (int m = 16; m >= 1; m >>= 1)
        acc += __shfl_xor_sync(0xffffffffu, acc, m);
    if (lane == 0) s_part[wid] = acc;
    __syncthreads();

    if (wid == 0) {
        float v = (lane < (TPB / 32)) ? s_part[lane] : 0.0f;
        #pragma unroll
        for (int m = 8; m >= 1; m >>= 1)
            v += __shfl_xor_sync(0xffffffffu, v, m);
        if (lane == 0)
            out[(long long)B * D + b] = 0.25f * v + __ldg(logdet_in + b);
    }
}

extern "C" void kernel_launch(void* const* d_in, const int* in_sizes, int n_in,
                              void* d_out, int out_size)
{
    const float* x   = (const float*)d_in[0];   // (B, D)
    const float* ld  = (const float*)d_in[1];   // (B,)
    const float* dsp = (const float*)d_in[2];   // (B, D, 48)
    float* out = (float*)d_out;

    const int B = in_sizes[1];
    const int D = in_sizes[0] / B;

    sigmoid_flow_kernel<<<B, TPB>>>(x, ld, dsp, out, B, D);
}